// round 3
// baseline (speedup 1.0000x reference)
#include <cuda_runtime.h>
#include <math.h>

#define BATCH    8
#define NCLS     80
#define NTOT     76725
#define CAND_TOT 4125
#define TOPN     1000
#define MAXDET   100
#define NEGV     (-1e9f)
#define MIN_SC   0.05f

// level geometry
#define N0 57600
#define N1 14400
#define N2 3600
#define N3 900
#define N4 225
// level offsets into per-batch score array
#define O1 57600
#define O2 72000
#define O3 75600
#define O4 76500
// candidate bases
#define C1 1000
#define C2 2000
#define C3 3000
#define C4 3900

#define NBC ((BATCH * NTOT + 255) / 256)   // compact blocks

// libdevice accurate expf — immune to --use_fast_math rewriting of expf->__expf.
extern "C" __device__ float __nv_expf(float);

// ---------------- scratch (device globals: no allocation allowed) ----------------
__device__ float         g_scores[BATCH * NTOT];
__device__ unsigned char g_cls  [BATCH * NTOT];
__device__ unsigned int  g_thr [BATCH * 3];   // exact bit-key of 1000th largest per (b, big level)
__device__ int           g_cgt [BATCH * 3];   // count(> T)
__device__ int           g_cnt [BATCH * 3];   // atomic compaction counters
__device__ float         g_cscore[BATCH * CAND_TOT];
__device__ unsigned int  g_cmeta [BATCH * CAND_TOT]; // (cls<<24)|(level<<16)|orig_idx
__device__ float4        g_cbox  [BATCH * CAND_TOT];

// monotonic float->uint key (handles negatives too)
__device__ __forceinline__ unsigned int fkey(float f) {
    unsigned int u = __float_as_uint(f);
    return (u & 0x80000000u) ? ~u : (u | 0x80000000u);
}

// Box decode, bit-matching the reference op order (no fma contraction; exact libdevice exp)
__device__ __forceinline__ float4 decode_box(const float4 rg, const float4 an) {
    float ww  = __fsub_rn(an.z, an.x);
    float hh  = __fsub_rn(an.w, an.y);
    float cx  = __fadd_rn(an.x, __fmul_rn(0.5f, ww));
    float cy  = __fadd_rn(an.y, __fmul_rn(0.5f, hh));
    float rx  = __fmul_rn(rg.x, 0.1f);
    float ry  = __fmul_rn(rg.y, 0.1f);
    float rw  = __fmul_rn(rg.z, 0.2f);
    float rh  = __fmul_rn(rg.w, 0.2f);
    float pw  = __fmul_rn(__nv_expf(rw), ww);
    float ph  = __fmul_rn(__nv_expf(rh), hh);
    float pcx = __fadd_rn(__fmul_rn(rx, ww), cx);
    float pcy = __fadd_rn(__fmul_rn(ry, hh), cy);
    int x1 = (int)__fsub_rn(pcx, __fmul_rn(0.5f, pw));   // trunc toward zero == astype(int32)
    int y1 = (int)__fsub_rn(pcy, __fmul_rn(0.5f, ph));
    int x2 = (int)__fadd_rn(pcx, __fmul_rn(0.5f, pw));
    int y2 = (int)__fadd_rn(pcy, __fmul_rn(0.5f, ph));
    x1 = max(x1, 0); y1 = max(y1, 0);
    x2 = min(x2, 639); y2 = min(y2, 639);
    return make_float4((float)x1, (float)y1, (float)x2, (float)y2);
}

// flat per-batch anchor index -> (level, local j, per-level count)
__device__ __forceinline__ void level_of(int jj, int& l, int& j, int& n) {
    if (jj < O1)      { l = 0; j = jj;      n = N0; }
    else if (jj < O2) { l = 1; j = jj - O1; n = N1; }
    else if (jj < O3) { l = 2; j = jj - O2; n = N2; }
    else if (jj < O4) { l = 3; j = jj - O3; n = N3; }
    else              { l = 4; j = jj - O4; n = N4; }
}

// ---------------- Kernel A (fused over all levels): max + argmax over 80 classes ----------------
__global__ void score_kernel(const float* __restrict__ c0, const float* __restrict__ c1,
                             const float* __restrict__ c2, const float* __restrict__ c3,
                             const float* __restrict__ c4) {
    int id = blockIdx.x * blockDim.x + threadIdx.x;
    if (id >= BATCH * NTOT) return;
    int b = id / NTOT, jj = id - b * NTOT;
    int l, j, n;
    level_of(jj, l, j, n);
    const float* base = (l == 0) ? c0 : (l == 1) ? c1 : (l == 2) ? c2 : (l == 3) ? c3 : c4;
    const float4* p = (const float4*)(base + ((size_t)b * n + j) * NCLS);
    float m = -1e30f; int a = 0;
#pragma unroll
    for (int i = 0; i < 20; i++) {
        float4 v = p[i];
        if (v.x > m) { m = v.x; a = 4 * i; }
        if (v.y > m) { m = v.y; a = 4 * i + 1; }
        if (v.z > m) { m = v.z; a = 4 * i + 2; }
        if (v.w > m) { m = v.w; a = 4 * i + 3; }
    }
    int o = b * NTOT + jj;
    g_scores[o] = m;
    g_cls[o] = (unsigned char)a;
}

// ---------------- Kernel B: exact 1000th-largest via MSB radix select ----------------
__global__ void topk_thresh_kernel() {
    const int NL[3] = {N0, N1, N2};
    const int LO[3] = {0, O1, O2};
    int bi = blockIdx.x;
    int b = bi / 3, l = bi % 3;
    int n = NL[l];
    const float* sc = g_scores + b * NTOT + LO[l];

    __shared__ unsigned int hist[256];
    __shared__ unsigned int s_prefix;
    __shared__ int s_krem, s_cgt;
    if (threadIdx.x == 0) { s_prefix = 0; s_krem = TOPN; s_cgt = 0; g_cnt[bi] = 0; }
    __syncthreads();

    for (int round = 0; round < 4; round++) {
        int shift = 24 - 8 * round;
        for (int i = threadIdx.x; i < 256; i += blockDim.x) hist[i] = 0;
        __syncthreads();
        unsigned int prefix = s_prefix;
        unsigned int pmask = (round == 0) ? 0u : (0xFFFFFFFFu << (shift + 8));
        for (int i = threadIdx.x; i < n; i += blockDim.x) {
            unsigned int k = fkey(sc[i]);
            if ((k & pmask) == prefix) atomicAdd(&hist[(k >> shift) & 255], 1);
        }
        __syncthreads();
        if (threadIdx.x == 0) {
            int krem = s_krem;
            unsigned int acc = 0;
            int bin = 255;
            for (; bin > 0; bin--) {
                unsigned int c = hist[bin];
                if (acc + c >= (unsigned int)krem) break;
                acc += c;
            }
            s_prefix = prefix | ((unsigned int)bin << shift);
            s_krem = krem - (int)acc;
            s_cgt += (int)acc;
        }
        __syncthreads();
    }
    if (threadIdx.x == 0) {
        g_thr[bi] = s_prefix;
        g_cgt[bi] = s_cgt;
    }
}

// ---------------- Kernel C (fused): compact (> T) + decode, plus fixup (== T) blocks ----------------
__global__ void compact_fixup_kernel(
    const float* __restrict__ r0, const float* __restrict__ r1, const float* __restrict__ r2,
    const float* __restrict__ r3, const float* __restrict__ r4,
    const float* __restrict__ a0, const float* __restrict__ a1, const float* __restrict__ a2,
    const float* __restrict__ a3, const float* __restrict__ a4) {

    __shared__ int list[512];
    __shared__ int cnt;

    if (blockIdx.x < NBC) {
        // ---- compact part: one thread per (batch, anchor) ----
        int id = blockIdx.x * blockDim.x + threadIdx.x;
        if (id >= BATCH * NTOT) return;
        int b = id / NTOT, jj = id - b * NTOT;
        int l, j, n;
        level_of(jj, l, j, n);
        float s = g_scores[b * NTOT + jj];
        int slot;
        if (l < 3) {
            if (fkey(s) <= g_thr[b * 3 + l]) return;
            int p = atomicAdd(&g_cnt[b * 3 + l], 1);
            if (p >= TOPN) return;   // safety (can't happen with exact radix select)
            slot = ((l == 0) ? 0 : (l == 1) ? C1 : C2) + p;
        } else {
            slot = ((l == 3) ? C3 : C4) + j;
        }
        const float* regp = (l == 0) ? r0 : (l == 1) ? r1 : (l == 2) ? r2 : (l == 3) ? r3 : r4;
        const float* ancp = (l == 0) ? a0 : (l == 1) ? a1 : (l == 2) ? a2 : (l == 3) ? a3 : a4;
        float4 rg = ((const float4*)regp)[(size_t)b * n + j];
        float4 an = ((const float4*)ancp)[(size_t)b * n + j];
        int o = b * CAND_TOT + slot;
        g_cscore[o] = s;
        g_cmeta[o]  = ((unsigned int)g_cls[b * NTOT + jj] << 24)
                    | ((unsigned int)l << 16) | (unsigned int)j;
        g_cbox[o]   = decode_box(rg, an);
    } else {
        // ---- fixup part: fill == T slots with the (TOPN - cgt) smallest orig indices ----
        const int NL[3] = {N0, N1, N2};
        const int LO[3] = {0, O1, O2};
        const int CB[3] = {0, C1, C2};
        int bi = blockIdx.x - NBC;          // 0..23
        int b = bi / 3, l = bi % 3;
        unsigned int T = g_thr[bi];
        int cgt = g_cgt[bi];
        int jt = TOPN - cgt;                // >= 1
        int n = NL[l];
        const float* sc = g_scores + b * NTOT + LO[l];

        if (threadIdx.x == 0) cnt = 0;
        __syncthreads();
        for (int i = threadIdx.x; i < n; i += blockDim.x) {
            if (fkey(sc[i]) == T) {
                int p = atomicAdd(&cnt, 1);
                if (p < 512) list[p] = i;
            }
        }
        __syncthreads();
        int m = min(cnt, 512);
        if (threadIdx.x == 0) {             // tiny insertion sort ascending (m is ~1-3)
            for (int i = 1; i < m; i++) {
                int v = list[i]; int k = i - 1;
                while (k >= 0 && list[k] > v) { list[k + 1] = list[k]; k--; }
                list[k + 1] = v;
            }
        }
        __syncthreads();
        const float* regp = (l == 0) ? r0 : ((l == 1) ? r1 : r2);
        const float* ancp = (l == 0) ? a0 : ((l == 1) ? a1 : a2);
        for (int i = threadIdx.x; i < jt; i += blockDim.x) {
            int o = b * CAND_TOT + CB[l] + cgt + i;
            if (i < m) {
                int j = list[i];
                float4 rg = ((const float4*)regp)[(size_t)b * n + j];
                float4 an = ((const float4*)ancp)[(size_t)b * n + j];
                g_cscore[o] = sc[j];
                g_cmeta[o]  = ((unsigned int)g_cls[b * NTOT + LO[l] + j] << 24)
                            | ((unsigned int)l << 16) | (unsigned int)j;
                g_cbox[o]   = decode_box(rg, an);
            } else {                        // unreachable filler, keep deterministic
                g_cscore[o] = NEGV;
                g_cmeta[o]  = (7u << 16);
                g_cbox[o]   = make_float4(0.f, 0.f, 0.f, 0.f);
            }
        }
    }
}

// ---------------- Kernel D: greedy NMS, 1 block/batch, register-resident ----------------
#define NMS_T 512
#define CPT   9     // 512*9 = 4608 >= 4125
__global__ __launch_bounds__(NMS_T, 1) void nms_kernel(float* __restrict__ out) {
    int b = blockIdx.x;
    int t = threadIdx.x;
    int lane = t & 31, warp = t >> 5;

    float live[CPT], x1[CPT], y1[CPT], x2[CPT], y2[CPT], area[CPT];
    unsigned int meta[CPT];
#pragma unroll
    for (int k = 0; k < CPT; k++) {
        int c = t + NMS_T * k;
        if (c < CAND_TOT) {
            float s   = g_cscore[b * CAND_TOT + c];
            float4 bx = g_cbox[b * CAND_TOT + c];
            meta[k] = g_cmeta[b * CAND_TOT + c];
            live[k] = (s > MIN_SC) ? s : NEGV;
            x1[k] = bx.x; y1[k] = bx.y; x2[k] = bx.z; y2[k] = bx.w;
            area[k] = (bx.z - bx.x) * (bx.w - bx.y);
        } else {
            live[k] = NEGV;
            meta[k] = (7u << 16) | (unsigned int)c;  // unique pad key
            x1[k] = y1[k] = x2[k] = y2[k] = 0.f;
            area[k] = 0.f;
        }
    }

    __shared__ unsigned long long s_wk[16];
    __shared__ unsigned long long s_final;
    __shared__ float s_bx[4];
    __shared__ float s_area;
    __shared__ int   s_has;

    float* outS = out + b * MAXDET;
    float* outC = out + BATCH * MAXDET + b * MAXDET;
    float* outB = out + 2 * BATCH * MAXDET + (size_t)b * MAXDET * 4;

    for (int det = 0; det < MAXDET; det++) {
        // local argmax; tie-break = earliest reference candidate position = min (level, orig_idx)
        unsigned long long mykey = 0ull; int bestk = 0;
#pragma unroll
        for (int k = 0; k < CPT; k++) {
            unsigned int u = __float_as_uint(live[k]);
            u = (u & 0x80000000u) ? ~u : (u | 0x80000000u);
            unsigned long long key = ((unsigned long long)u << 24)
                | (unsigned long long)(0x00FFFFFFu - (meta[k] & 0x00FFFFFFu));
            if (key > mykey) { mykey = key; bestk = k; }
        }
        unsigned long long rk = mykey;
#pragma unroll
        for (int off = 16; off; off >>= 1) {
            unsigned long long o = __shfl_down_sync(0xFFFFFFFFu, rk, off);
            if (o > rk) rk = o;
        }
        if (lane == 0) s_wk[warp] = rk;
        __syncthreads();
        if (warp == 0) {
            unsigned long long v = s_wk[lane & 15];
#pragma unroll
            for (int off = 16; off; off >>= 1) {
                unsigned long long o = __shfl_down_sync(0xFFFFFFFFu, v, off);
                if (o > v) v = o;
            }
            if (lane == 0) s_final = v;
        }
        __syncthreads();

        if (mykey == s_final) {   // unique winner (keys carry unique meta)
#pragma unroll
            for (int k = 0; k < CPT; k++) {
                if (k == bestk) {
                    float sc = live[k];
                    int has = sc > (NEGV * 0.5f);
                    s_bx[0] = x1[k]; s_bx[1] = y1[k]; s_bx[2] = x2[k]; s_bx[3] = y2[k];
                    s_area = area[k];
                    s_has = has;
                    live[k] = NEGV;                        // remove selected (unconditional, as ref)
                    outS[det] = has ? sc : -1.0f;
                    outC[det] = has ? (float)(meta[k] >> 24) : -1.0f;
                    float4 ob = has ? make_float4(x1[k], y1[k], x2[k], y2[k])
                                    : make_float4(-1.f, -1.f, -1.f, -1.f);
                    ((float4*)outB)[det] = ob;
                }
            }
        }
        __syncthreads();

        if (s_has) {
            float wx1 = s_bx[0], wy1 = s_bx[1], wx2 = s_bx[2], wy2 = s_bx[3], wa = s_area;
#pragma unroll
            for (int k = 0; k < CPT; k++) {
                float tlx = fmaxf(x1[k], wx1), tly = fmaxf(y1[k], wy1);
                float brx = fminf(x2[k], wx2), bry = fminf(y2[k], wy2);
                float w = fmaxf(brx - tlx, 0.f), h = fmaxf(bry - tly, 0.f);
                float inter = w * h;
                // exact integer equivalence of inter/max(union,1e-4) >= 0.5 (inter>0 guards clamp path)
                if (inter > 0.f && 3.0f * inter >= area[k] + wa) live[k] = NEGV;
            }
        }
        // next iteration's first barrier protects s_* reuse
    }
}

// ---------------- launch ----------------
extern "C" void kernel_launch(void* const* d_in, const int* in_sizes, int n_in,
                              void* d_out, int out_size) {
    (void)n_in; (void)out_size;

    // Autodetect input ordering:
    //  interleaved (setup_inputs dict order): cls0,reg0,anc0,cls1,...  -> in_sizes[1] == 8*57600*4
    //  grouped (reference signature order):   cls0..4,reg0..4,anc0..4 -> in_sizes[1] == 8*14400*80
    int interleaved = (in_sizes[1] == BATCH * N0 * 4) ? 1 : 0;
    const float* CLS[5]; const float* REG[5]; const float* ANC[5];
    for (int l = 0; l < 5; l++) {
        if (interleaved) {
            CLS[l] = (const float*)d_in[3 * l];
            REG[l] = (const float*)d_in[3 * l + 1];
            ANC[l] = (const float*)d_in[3 * l + 2];
        } else {
            CLS[l] = (const float*)d_in[l];
            REG[l] = (const float*)d_in[5 + l];
            ANC[l] = (const float*)d_in[10 + l];
        }
    }

    score_kernel<<<NBC, 256>>>(CLS[0], CLS[1], CLS[2], CLS[3], CLS[4]);
    topk_thresh_kernel<<<24, 256>>>();
    compact_fixup_kernel<<<NBC + 24, 256>>>(REG[0], REG[1], REG[2], REG[3], REG[4],
                                            ANC[0], ANC[1], ANC[2], ANC[3], ANC[4]);
    nms_kernel<<<BATCH, NMS_T>>>((float*)d_out);
}